// round 15
// baseline (speedup 1.0000x reference)
#include <cuda_runtime.h>
#include <cuda_bf16.h>
#include <cstddef>
#include <cstdint>

#define N_ENT   100000
#define N_REL   18
#define N_TRI   600000
#define BSZ     64
#define MAXQ    32
#define DH      300
#define D_CLS   1024
#define NB_CSR  148
#define G1_OPB  680
#define NTILES  ((N_ENT + 255) / 256)   // 391

// ---------------- scratch (static device globals: no allocation) -------------
__device__ float g_eA[(size_t)N_ENT * BSZ];
__device__ float g_eB[(size_t)N_ENT * BSZ];
__device__ float g_lastc[BSZ * DH];
__device__ float g_relT[N_REL * BSZ];
__device__ float g_predAcc[BSZ * DH + BSZ];
__device__ __nv_bfloat16 g_hh[BSZ * D_CLS];
__device__ __nv_bfloat16 g_hl[BSZ * D_CLS];
__device__ int g_cnt[N_ENT + 1];
__device__ int g_off[N_ENT + 1];
__device__ int g_pos[N_ENT];
__device__ int2 g_srS[N_TRI];
__device__ int g_bsum[NB_CSR];
__device__ int g_bbase[NB_CSR];
__device__ unsigned g_barrier;

// ---------------- helpers ----------------------------------------------------
__device__ __forceinline__ float warp_sum(float v) {
    #pragma unroll
    for (int o = 16; o; o >>= 1) v += __shfl_xor_sync(0xffffffffu, v, o);
    return v;
}
__device__ __forceinline__ float warp_max(float v) {
    #pragma unroll
    for (int o = 16; o; o >>= 1) v = fmaxf(v, __shfl_xor_sync(0xffffffffu, v, o));
    return v;
}
__device__ __forceinline__ unsigned long long pk2(float lo, float hi) {
    unsigned long long r;
    asm("mov.b64 %0, {%1, %2};" : "=l"(r) : "f"(lo), "f"(hi));
    return r;
}
__device__ __forceinline__ float2 upk(unsigned long long v) {
    float2 r;
    asm("mov.b64 {%0, %1}, %2;" : "=f"(r.x), "=f"(r.y) : "l"(v));
    return r;
}
__device__ __forceinline__ void fma2(unsigned long long& d, unsigned long long a,
                                     unsigned long long b) {
    asm("fma.rn.f32x2 %0, %1, %2, %0;" : "+l"(d) : "l"(a), "l"(b));
}
__device__ __forceinline__ uint32_t s2u(const void* p) {
    return (uint32_t)__cvta_generic_to_shared(p);
}
__device__ __forceinline__ void cpa16(uint32_t d, const void* s) {
    asm volatile("cp.async.cg.shared.global [%0], [%1], 16;" :: "r"(d), "l"(s));
}
#define CPA_COMMIT() asm volatile("cp.async.commit_group;")
#define CPA_WAIT(N)  asm volatile("cp.async.wait_group %0;" :: "n"(N))

__device__ __forceinline__ void cpa_wait_tail(int g, int ng) {
    if (g < ng - 2)      CPA_WAIT(2);
    else if (g == ng - 2) CPA_WAIT(1);
    else                  CPA_WAIT(0);
}

// software grid barrier
__device__ __forceinline__ void gsync() {
    __syncthreads();
    if (threadIdx.x == 0) {
        __threadfence();
        unsigned old = atomicAdd(&g_barrier, 1u);
        unsigned goal = old - (old % (unsigned)NB_CSR) + (unsigned)NB_CSR;
        while (true) {
            unsigned cur = *(volatile unsigned*)&g_barrier;
            if ((int)(cur - goal) >= 0) break;
        }
        __threadfence();
    }
    __syncthreads();
}

// bf16 helpers
__device__ __forceinline__ uint32_t bfpack(float x, float y) {
    __nv_bfloat162 t = __floats2bfloat162_rn(x, y);
    return *reinterpret_cast<uint32_t*>(&t);
}
__device__ __forceinline__ void mma_bf16(float* d, uint32_t a0, uint32_t a1,
                                         uint32_t a2, uint32_t a3,
                                         uint32_t b0, uint32_t b1) {
    asm volatile(
        "mma.sync.aligned.m16n8k16.row.col.f32.bf16.bf16.f32 "
        "{%0,%1,%2,%3}, {%4,%5,%6,%7}, {%8,%9}, {%0,%1,%2,%3};"
        : "+f"(d[0]), "+f"(d[1]), "+f"(d[2]), "+f"(d[3])
        : "r"(a0), "r"(a1), "r"(a2), "r"(a3), "r"(b0), "r"(b1));
}

// ---------------- K: transpose e_s [64,N_ENT] -> eT [N_ENT,64] ---------------
__global__ void transpose_kernel(const float* __restrict__ in, float* __restrict__ out) {
    __shared__ float tile[32][33];
    int tx = threadIdx.x, ty = threadIdx.y;
    int o_in = blockIdx.x * 32 + tx;
    int b_in = blockIdx.y * 32 + ty;
    tile[ty][tx] = in[(size_t)b_in * N_ENT + o_in];
    __syncthreads();
    int o_out = blockIdx.x * 32 + ty;
    int b_out = blockIdx.y * 32 + tx;
    out[(size_t)o_out * BSZ + b_out] = tile[tx][ty];
}

// ---------------- K: full CSR build in one persistent kernel -----------------
__global__ void __launch_bounds__(1024, 1)
csr_kernel(const int* __restrict__ subj, const int* __restrict__ rel,
           const int* __restrict__ obj, int* __restrict__ cnt,
           int* __restrict__ off, int* __restrict__ pos,
           int2* __restrict__ srS, int* __restrict__ bsum, int* __restrict__ bbase,
           float* __restrict__ predAcc) {
    __shared__ int s_scan[1024];
    __shared__ int s_b[256];
    const int tid = threadIdx.x, bid = blockIdx.x;
    const int gtid = bid * 1024 + tid;
    const int gstride = NB_CSR * 1024;

    for (int i = gtid; i <= N_ENT; i += gstride) cnt[i] = 0;
    for (int i = gtid; i < BSZ * DH + BSZ; i += gstride) predAcc[i] = 0.f;
    gsync();

    for (int t = gtid; t < N_TRI; t += gstride) atomicAdd(&cnt[obj[t]], 1);
    gsync();

    constexpr int CH = (N_ENT + NB_CSR - 1) / NB_CSR;  // 676
    const int base = bid * CH;
    const int m = min(CH, N_ENT - base);
    int val = (tid < m) ? cnt[base + tid] : 0;
    s_scan[tid] = val;
    __syncthreads();
    #pragma unroll
    for (int d = 1; d < 1024; d <<= 1) {
        int v = (tid >= d) ? s_scan[tid - d] : 0;
        __syncthreads();
        s_scan[tid] += v;
        __syncthreads();
    }
    int excl = s_scan[tid] - val;
    if (tid == 1023) bsum[bid] = s_scan[1023];
    gsync();

    if (bid == 0) {
        int bv = (tid < NB_CSR) ? bsum[tid] : 0;
        if (tid < 256) s_b[tid] = bv;
        __syncthreads();
        #pragma unroll
        for (int d = 1; d < 256; d <<= 1) {
            int v = 0;
            if (tid < 256 && tid >= d) v = s_b[tid - d];
            __syncthreads();
            if (tid < 256) s_b[tid] += v;
            __syncthreads();
        }
        if (tid < NB_CSR) bbase[tid] = s_b[tid] - bv;
    }
    gsync();

    int bb = bbase[bid];
    if (tid < m) {
        off[base + tid] = bb + excl;
        pos[base + tid] = bb + excl;
    }
    if (gtid == 0) off[N_ENT] = N_TRI;
    gsync();

    for (int t = gtid; t < N_TRI; t += gstride) {
        int o = obj[t];
        int p = atomicAdd(&pos[o], 1);
        srS[p] = make_int2(subj[t], rel[t]);
    }
}

// ---------------- per-step dense math (one block per batch row) --------------
__global__ void step_kernel(const float* __restrict__ qwh, const float* __restrict__ qemb,
                            const float* __restrict__ Wstep, const float* __restrict__ bstep,
                            const float* __restrict__ Wcq, const float* __restrict__ bcq,
                            const float* __restrict__ Wca, const float* __restrict__ bca,
                            const float* __restrict__ Wrel, const float* __restrict__ brel,
                            float* __restrict__ lastc, float* __restrict__ relT, int t) {
    __shared__ float s_qe[DH], s_lc[DH], s_qt[DH], s_cw[DH];
    __shared__ float s_log[MAXQ], s_dist[MAXQ];
    int b = blockIdx.x, tid = threadIdx.x;

    if (tid < DH) {
        s_qe[tid] = qemb[b * DH + tid];
        s_lc[tid] = (t == 0) ? 0.f : lastc[b * DH + tid];
    }
    __syncthreads();

    if (tid < DH) {
        const float* W = Wstep + t * DH * DH;
        float acc = bstep[t * DH + tid];
        for (int k = 0; k < DH; ++k) acc = fmaf(s_qe[k], W[k * DH + tid], acc);
        s_qt[tid] = tanhf(acc);
    }
    __syncthreads();

    if (tid < DH) {
        float acc = bcq[tid];
        if (t != 0)
            for (int k = 0; k < DH; ++k) acc = fmaf(s_lc[k], Wcq[k * DH + tid], acc);
        for (int k = 0; k < DH; ++k) acc = fmaf(s_qt[k], Wcq[(DH + k) * DH + tid], acc);
        s_cw[tid] = acc * Wca[tid];
    }
    __syncthreads();

    {
        int w = tid >> 5, lane = tid & 31;
        for (int q = w; q < MAXQ; q += 10) {
            const float* row = qwh + ((size_t)b * MAXQ + q) * DH;
            float acc = 0.f;
            for (int d = lane; d < DH; d += 32) acc = fmaf(s_cw[d], row[d], acc);
            acc = warp_sum(acc);
            if (lane == 0) s_log[q] = acc + bca[0];
        }
    }
    __syncthreads();

    if (tid < 32) {
        float v = s_log[tid];
        float m = warp_max(v);
        float e = expf(v - m);
        float s = warp_sum(e);
        s_dist[tid] = e / s;
    }
    __syncthreads();

    if (tid < DH) {
        const float* base = qwh + (size_t)b * MAXQ * DH + tid;
        float acc = 0.f;
        #pragma unroll
        for (int q = 0; q < MAXQ; ++q) acc = fmaf(s_dist[q], base[q * DH], acc);
        s_lc[tid] = acc;
        lastc[b * DH + tid] = acc;
    }
    __syncthreads();

    if (tid < 32) {
        float val = -1e30f;
        if (tid < N_REL) {
            float acc = brel[tid];
            for (int d = 0; d < DH; ++d) acc = fmaf(s_lc[d], Wrel[d * N_REL + tid], acc);
            val = acc;
        }
        float m = warp_max(val);
        float e = (tid < N_REL) ? expf(val - m) : 0.f;
        float s = warp_sum(e);
        if (tid < N_REL) relT[tid * BSZ + b] = e / s;
    }
}

// ---------------- follow via CSR: warp per object, 2-way unrolled ------------
__global__ void follow_kernel(const float* __restrict__ eCur, const float* __restrict__ relT,
                              const int* __restrict__ off, const int2* __restrict__ srS,
                              float* __restrict__ eNext) {
    int o = blockIdx.x * 8 + (threadIdx.x >> 5);
    int lane = threadIdx.x & 31;
    int beg = __ldg(off + o), end = __ldg(off + o + 1);
    float2 a0 = make_float2(0.f, 0.f);
    float2 a1 = make_float2(0.f, 0.f);
    int t = beg;
    for (; t + 1 < end; t += 2) {
        int2 s0 = __ldg(srS + t);
        int2 s1 = __ldg(srS + t + 1);
        float2 e0 = *reinterpret_cast<const float2*>(eCur + (size_t)s0.x * BSZ + 2 * lane);
        float2 r0 = *reinterpret_cast<const float2*>(relT + s0.y * BSZ + 2 * lane);
        float2 e1 = *reinterpret_cast<const float2*>(eCur + (size_t)s1.x * BSZ + 2 * lane);
        float2 r1 = *reinterpret_cast<const float2*>(relT + s1.y * BSZ + 2 * lane);
        a0.x = fmaf(e0.x, r0.x, a0.x);
        a0.y = fmaf(e0.y, r0.y, a0.y);
        a1.x = fmaf(e1.x, r1.x, a1.x);
        a1.y = fmaf(e1.y, r1.y, a1.y);
    }
    if (t < end) {
        int2 s0 = __ldg(srS + t);
        float2 e0 = *reinterpret_cast<const float2*>(eCur + (size_t)s0.x * BSZ + 2 * lane);
        float2 r0 = *reinterpret_cast<const float2*>(relT + s0.y * BSZ + 2 * lane);
        a0.x = fmaf(e0.x, r0.x, a0.x);
        a0.y = fmaf(e0.y, r0.y, a0.y);
    }
    *reinterpret_cast<float2*>(eNext + (size_t)o * BSZ + 2 * lane) =
        make_float2(a0.x + a1.x, a0.y + a1.y);
}

// ---------------- GEMM1 (pipelined fp32): predAcc = eT^T @ emb ---------------
__global__ void __launch_bounds__(512, 1)
gemm1_kernel(const float* __restrict__ eT, const float* __restrict__ emb,
             float* __restrict__ predAcc) {
    extern __shared__ char sm1[];
    float* we = (float*)sm1;                       // [4][8][320]
    float* es = (float*)(sm1 + 4 * 8 * 320 * 4);   // [4][8][64]
    const int tid = threadIdx.x, lane = tid & 31, w = tid >> 5;
    const int b0 = w * 4;
    const int o0 = blockIdx.x * G1_OPB;
    const int m  = min(G1_OPB, N_ENT - o0);
    const int ng = (m + 7) >> 3;

    for (int i = tid; i < 4 * 8 * 20; i += 512) {
        int st = i / 160, rem = i % 160, row = rem / 20, c = 300 + rem % 20;
        we[st * 2560 + row * 320 + c] = 0.f;
    }

    unsigned long long acc[4][5];
    #pragma unroll
    for (int bi = 0; bi < 4; ++bi)
        #pragma unroll
        for (int j = 0; j < 5; ++j) acc[bi][j] = 0ull;
    float sum4[4] = {0.f, 0.f, 0.f, 0.f};

    auto issue = [&](int g) {
        int stage = g & 3;
        int ob = g * 8;
        #pragma unroll
        for (int r = 0; r < 2; ++r) {
            int idx = tid + r * 512;
            if (idx < 600) {
                int kk = idx / 75, f = idx % 75;
                int o = o0 + ob + kk;
                float* dst = &we[stage * 2560 + kk * 320 + f * 4];
                if (o < N_ENT) cpa16(s2u(dst), emb + (size_t)o * DH + f * 4);
                else *(float4*)dst = make_float4(0.f, 0.f, 0.f, 0.f);
            } else if (idx < 728) {
                int j = idx - 600;
                int kk = j >> 4, q = j & 15;
                int o = o0 + ob + kk;
                float* dst = &es[stage * 512 + kk * 64 + q * 4];
                if (o < N_ENT) cpa16(s2u(dst), eT + (size_t)o * BSZ + q * 4);
                else *(float4*)dst = make_float4(0.f, 0.f, 0.f, 0.f);
            }
        }
        CPA_COMMIT();
    };

    issue(0); issue(1); issue(2);

    for (int g = 0; g < ng; ++g) {
        cpa_wait_tail(g, ng);
        __syncthreads();
        int stage = g & 3;
        #pragma unroll 4
        for (int kk = 0; kk < 8; ++kk) {
            float4 e4 = *(const float4*)&es[stage * 512 + kk * 64 + b0];
            unsigned long long h0 = pk2(e4.x, e4.x), h1 = pk2(e4.y, e4.y);
            unsigned long long h2 = pk2(e4.z, e4.z), h3 = pk2(e4.w, e4.w);
            sum4[0] += e4.x; sum4[1] += e4.y; sum4[2] += e4.z; sum4[3] += e4.w;
            const float* wr = &we[stage * 2560 + kk * 320];
            #pragma unroll
            for (int j = 0; j < 5; ++j) {
                unsigned long long wv =
                    *(const unsigned long long*)(wr + (lane + 32 * j) * 2);
                fma2(acc[0][j], wv, h0);
                fma2(acc[1][j], wv, h1);
                fma2(acc[2][j], wv, h2);
                fma2(acc[3][j], wv, h3);
            }
        }
        __syncthreads();
        if (g + 3 < ng) issue(g + 3);
    }
    CPA_WAIT(0);

    #pragma unroll
    for (int j = 0; j < 5; ++j) {
        int dp = lane + 32 * j;
        if (dp < 150) {
            #pragma unroll
            for (int bi = 0; bi < 4; ++bi) {
                float2 a = upk(acc[bi][j]);
                atomicAdd(&predAcc[(b0 + bi) * DH + 2 * dp], a.x);
                atomicAdd(&predAcc[(b0 + bi) * DH + 2 * dp + 1], a.y);
            }
        }
    }
    if (lane == 0) {
        #pragma unroll
        for (int bi = 0; bi < 4; ++bi)
            atomicAdd(&predAcc[BSZ * DH + b0 + bi], sum4[bi]);
    }
}

// ---------------- h = relu(...) -> bf16 hi/lo arrays -------------------------
__global__ void h_kernel(const float* __restrict__ predAcc, const float* __restrict__ We1,
                         const float* __restrict__ be1,
                         __nv_bfloat16* __restrict__ hh, __nv_bfloat16* __restrict__ hl) {
    __shared__ float s_p[DH];
    int b = blockIdx.x, tid = threadIdx.x;
    float inv = 1.f / (predAcc[BSZ * DH + b] + 1e-6f);
    for (int i = tid; i < DH; i += 256) s_p[i] = predAcc[b * DH + i] * inv;
    __syncthreads();
    int d = blockIdx.y * 256 + tid;
    float acc = be1[d];
    for (int k = 0; k < DH; ++k) acc = fmaf(s_p[k], We1[k * D_CLS + d], acc);
    float v = fmaxf(acc, 0.f);
    __nv_bfloat16 hi = __float2bfloat16(v);
    hh[b * D_CLS + d] = hi;
    hl[b * D_CLS + d] = __float2bfloat16(v - __bfloat162float(hi));
}

// ---------------- GEMM2: HMMA bf16-split, staged-convert B -------------------
// Persistent 148 blocks x 391 tiles of 256 n; per tile 32 k-chunks of 32.
// We2 chunk staged fp32 via cp.async (double buf [2][32][260]); then ONE
// block-wide pass converts+transposes to bf16 hi/lo planes [n=256][kpair pitch
// 20 words] (fragment read: addr = nc*20 + ks*8 + t (+4) -> conflict-free).
// mma.sync m16n8k16: D += Ah*Bh + Ah*Bl + Al*Bh.
#define G2_KC    32
#define G2_NGC   (D_CLS / G2_KC)            // 32 chunks
#define G2_ROWW  260
#define BS_WORDS (2 * G2_KC * G2_ROWW)      // 16640
#define BH_PITCH 20
#define BH_OFF   BS_WORDS
#define BL_OFF   (BS_WORDS + 256 * BH_PITCH)
#define G2_SMEM  ((BS_WORDS + 2 * 256 * BH_PITCH) * 4)   // 107520 B

__global__ void __launch_bounds__(512, 1)
gemm2_kernel(const __nv_bfloat16* __restrict__ hh, const __nv_bfloat16* __restrict__ hl,
             const float* __restrict__ We2, const float* __restrict__ be2,
             float* __restrict__ out) {
    extern __shared__ float Bs[];
    uint32_t* Bw = (uint32_t*)Bs;
    const int tid = threadIdx.x, lane = tid & 31, w = tid >> 5;  // 16 warps
    const int g = lane >> 2, t = lane & 3;
    const int m0 = (w & 3) * 16;          // m-tile
    const int nbase = (w >> 2) * 64;      // n-range within 256

    for (int tile = blockIdx.x; tile < NTILES; tile += 148) {
        const int n0 = tile * 256;

        float acc[8][4];
        #pragma unroll
        for (int s = 0; s < 8; ++s)
            #pragma unroll
            for (int j = 0; j < 4; ++j) acc[s][j] = 0.f;

        auto issue = [&](int c) {
            int buf = c & 1;
            int k0 = c * G2_KC;
            #pragma unroll
            for (int r = 0; r < 4; ++r) {
                int u = tid + r * 512;            // 0..2047
                int row = u >> 6, q = u & 63;
                float* dst = &Bs[buf * G2_KC * G2_ROWW + row * G2_ROWW + q * 4];
                int n = n0 + q * 4;
                if (n < N_ENT)
                    cpa16(s2u(dst), We2 + (size_t)(k0 + row) * N_ENT + n);
                else
                    *(float4*)dst = make_float4(0.f, 0.f, 0.f, 0.f);
            }
            CPA_COMMIT();
        };

        issue(0);

        for (int c = 0; c < G2_NGC; ++c) {
            if (c + 1 < G2_NGC) { issue(c + 1); CPA_WAIT(1); }
            else { CPA_WAIT(0); }
            __syncthreads();   // chunk c landed; also: compute(c-1) done

            // convert+transpose chunk c: fp32 [k][n] -> bf16 hi/lo [n][kpair]
            const float* B = &Bs[(c & 1) * G2_KC * G2_ROWW];
            #pragma unroll
            for (int r = 0; r < 8; ++r) {
                int u = tid + r * 512;       // 0..4095
                int kp = u >> 8, n = u & 255;
                float b0 = B[(2 * kp) * G2_ROWW + n];
                float b1 = B[(2 * kp + 1) * G2_ROWW + n];
                uint32_t hi = bfpack(b0, b1);
                __nv_bfloat162 h2 = *reinterpret_cast<__nv_bfloat162*>(&hi);
                float2 hf = __bfloat1622float2(h2);
                uint32_t lo = bfpack(b0 - hf.x, b1 - hf.y);
                Bw[BH_OFF + n * BH_PITCH + kp] = hi;
                Bw[BL_OFF + n * BH_PITCH + kp] = lo;
            }
            __syncthreads();

            const int kb = c * G2_KC;
            #pragma unroll
            for (int ks = 0; ks < 2; ++ks) {
                const int ka = kb + ks * 16 + 2 * t;
                const __nv_bfloat16* pa0 = hh + (m0 + g) * D_CLS + ka;
                const __nv_bfloat16* pa1 = hh + (m0 + g + 8) * D_CLS + ka;
                uint32_t ah0 = *(const uint32_t*)pa0;
                uint32_t ah1 = *(const uint32_t*)pa1;
                uint32_t ah2 = *(const uint32_t*)(pa0 + 8);
                uint32_t ah3 = *(const uint32_t*)(pa1 + 8);
                const __nv_bfloat16* pl0 = hl + (m0 + g) * D_CLS + ka;
                const __nv_bfloat16* pl1 = hl + (m0 + g + 8) * D_CLS + ka;
                uint32_t al0 = *(const uint32_t*)pl0;
                uint32_t al1 = *(const uint32_t*)pl1;
                uint32_t al2 = *(const uint32_t*)(pl0 + 8);
                uint32_t al3 = *(const uint32_t*)(pl1 + 8);

                #pragma unroll
                for (int sub = 0; sub < 8; ++sub) {
                    int nc = nbase + sub * 8 + g;
                    int base = nc * BH_PITCH + ks * 8 + t;
                    uint32_t bh0 = Bw[BH_OFF + base];
                    uint32_t bh1 = Bw[BH_OFF + base + 4];
                    uint32_t bl0 = Bw[BL_OFF + base];
                    uint32_t bl1 = Bw[BL_OFF + base + 4];
                    mma_bf16(acc[sub], ah0, ah1, ah2, ah3, bh0, bh1);
                    mma_bf16(acc[sub], ah0, ah1, ah2, ah3, bl0, bl1);
                    mma_bf16(acc[sub], al0, al1, al2, al3, bh0, bh1);
                }
            }
        }
        __syncthreads();

        // output: rows m0+g / m0+g+8, cols n0+nbase+sub*8+2t (+1)
        #pragma unroll
        for (int sub = 0; sub < 8; ++sub) {
            int n = n0 + nbase + sub * 8 + 2 * t;
            if (n < N_ENT) {
                float2 bb = *(const float2*)(be2 + n);
                int r0 = m0 + g, r1 = m0 + g + 8;
                *(float2*)(out + (size_t)r0 * N_ENT + n) =
                    make_float2(acc[sub][0] + bb.x, acc[sub][1] + bb.y);
                *(float2*)(out + (size_t)r1 * N_ENT + n) =
                    make_float2(acc[sub][2] + bb.x, acc[sub][3] + bb.y);
            }
        }
        __syncthreads();
    }
}

// ---------------- launch -----------------------------------------------------
extern "C" void kernel_launch(void* const* d_in, const int* in_sizes, int n_in,
                              void* d_out, int out_size) {
    const float* qwh   = (const float*)d_in[0];
    const float* qemb  = (const float*)d_in[1];
    const float* e_s   = (const float*)d_in[2];
    const float* Wstep = (const float*)d_in[3];
    const float* bstep = (const float*)d_in[4];
    const float* Wcq   = (const float*)d_in[5];
    const float* bcq   = (const float*)d_in[6];
    const float* Wca   = (const float*)d_in[7];
    const float* bca   = (const float*)d_in[8];
    const float* Wrel  = (const float*)d_in[9];
    const float* brel  = (const float*)d_in[10];
    const float* emb   = (const float*)d_in[11];
    const float* We1   = (const float*)d_in[12];
    const float* be1   = (const float*)d_in[13];
    const float* We2   = (const float*)d_in[14];
    const float* be2   = (const float*)d_in[15];
    const int*   subj  = (const int*)d_in[16];
    const int*   rel   = (const int*)d_in[17];
    const int*   obj   = (const int*)d_in[18];
    float* out = (float*)d_out;

    float *eA, *eB, *lastc, *relT, *predAcc;
    __nv_bfloat16 *hh, *hl;
    int *cnt, *off, *pos, *bsum, *bbase;
    int2* srS;
    cudaGetSymbolAddress((void**)&eA, g_eA);
    cudaGetSymbolAddress((void**)&eB, g_eB);
    cudaGetSymbolAddress((void**)&lastc, g_lastc);
    cudaGetSymbolAddress((void**)&relT, g_relT);
    cudaGetSymbolAddress((void**)&predAcc, g_predAcc);
    cudaGetSymbolAddress((void**)&hh, g_hh);
    cudaGetSymbolAddress((void**)&hl, g_hl);
    cudaGetSymbolAddress((void**)&cnt, g_cnt);
    cudaGetSymbolAddress((void**)&off, g_off);
    cudaGetSymbolAddress((void**)&pos, g_pos);
    cudaGetSymbolAddress((void**)&srS, g_srS);
    cudaGetSymbolAddress((void**)&bsum, g_bsum);
    cudaGetSymbolAddress((void**)&bbase, g_bbase);

    const int SM1 = 4 * 8 * 320 * 4 + 4 * 8 * 64 * 4; // 49152
    cudaFuncSetAttribute(gemm2_kernel, cudaFuncAttributeMaxDynamicSharedMemorySize,
                         G2_SMEM);
    cudaFuncSetAttribute(gemm1_kernel, cudaFuncAttributeMaxDynamicSharedMemorySize, SM1);

    transpose_kernel<<<dim3(N_ENT / 32, BSZ / 32), dim3(32, 32)>>>(e_s, eA);
    step_kernel<<<BSZ, 320>>>(qwh, qemb, Wstep, bstep, Wcq, bcq, Wca, bca,
                              Wrel, brel, lastc, relT, 0);
    csr_kernel<<<NB_CSR, 1024>>>(subj, rel, obj, cnt, off, pos, srS, bsum, bbase,
                                 predAcc);

    float* cur = eA;
    float* nxt = eB;
    for (int t = 0; t < 3; ++t) {
        if (t > 0)
            step_kernel<<<BSZ, 320>>>(qwh, qemb, Wstep, bstep, Wcq, bcq, Wca, bca,
                                      Wrel, brel, lastc, relT, t);
        follow_kernel<<<N_ENT / 8, 256>>>(cur, relT, off, srS, nxt);
        float* tmp = cur; cur = nxt; nxt = tmp;
    }

    gemm1_kernel<<<148, 512, SM1>>>(cur, emb, predAcc);
    h_kernel<<<dim3(BSZ, D_CLS / 256), 256>>>(predAcc, We1, be1, hh, hl);
    gemm2_kernel<<<148, 512, G2_SMEM>>>(hh, hl, We2, be2, out);
}

// round 17
// speedup vs baseline: 1.0603x; 1.0603x over previous
#include <cuda_runtime.h>
#include <cuda_bf16.h>
#include <cstddef>
#include <cstdint>

#define N_ENT   100000
#define N_REL   18
#define N_TRI   600000
#define BSZ     64
#define MAXQ    32
#define DH      300
#define D_CLS   1024
#define NB_CSR  148
#define G1_OPB  680
#define NTILES  ((N_ENT + 255) / 256)   // 391

// ---------------- scratch (static device globals: no allocation) -------------
__device__ float g_eA[(size_t)N_ENT * BSZ];
__device__ float g_eB[(size_t)N_ENT * BSZ];
__device__ float g_lastc[BSZ * DH];
__device__ float g_relT[N_REL * BSZ];
__device__ float g_predAcc[BSZ * DH + BSZ];
__device__ __nv_bfloat16 g_hh[BSZ * D_CLS];
__device__ __nv_bfloat16 g_hl[BSZ * D_CLS];
__device__ int g_cnt[N_ENT + 1];
__device__ int g_off[N_ENT + 1];
__device__ int g_pos[N_ENT];
__device__ int2 g_srS[N_TRI];
__device__ int g_bsum[NB_CSR];
__device__ int g_bbase[NB_CSR];
__device__ unsigned g_barrier;

// ---------------- helpers ----------------------------------------------------
__device__ __forceinline__ float warp_sum(float v) {
    #pragma unroll
    for (int o = 16; o; o >>= 1) v += __shfl_xor_sync(0xffffffffu, v, o);
    return v;
}
__device__ __forceinline__ float warp_max(float v) {
    #pragma unroll
    for (int o = 16; o; o >>= 1) v = fmaxf(v, __shfl_xor_sync(0xffffffffu, v, o));
    return v;
}
__device__ __forceinline__ unsigned long long pk2(float lo, float hi) {
    unsigned long long r;
    asm("mov.b64 %0, {%1, %2};" : "=l"(r) : "f"(lo), "f"(hi));
    return r;
}
__device__ __forceinline__ float2 upk(unsigned long long v) {
    float2 r;
    asm("mov.b64 {%0, %1}, %2;" : "=f"(r.x), "=f"(r.y) : "l"(v));
    return r;
}
__device__ __forceinline__ void fma2(unsigned long long& d, unsigned long long a,
                                     unsigned long long b) {
    asm("fma.rn.f32x2 %0, %1, %2, %0;" : "+l"(d) : "l"(a), "l"(b));
}
__device__ __forceinline__ uint32_t s2u(const void* p) {
    return (uint32_t)__cvta_generic_to_shared(p);
}
__device__ __forceinline__ void cpa16(uint32_t d, const void* s) {
    asm volatile("cp.async.cg.shared.global [%0], [%1], 16;" :: "r"(d), "l"(s));
}
#define CPA_COMMIT() asm volatile("cp.async.commit_group;")
#define CPA_WAIT(N)  asm volatile("cp.async.wait_group %0;" :: "n"(N))

__device__ __forceinline__ void cpa_wait_tail(int g, int ng) {
    if (g < ng - 2)      CPA_WAIT(2);
    else if (g == ng - 2) CPA_WAIT(1);
    else                  CPA_WAIT(0);
}

// software grid barrier
__device__ __forceinline__ void gsync() {
    __syncthreads();
    if (threadIdx.x == 0) {
        __threadfence();
        unsigned old = atomicAdd(&g_barrier, 1u);
        unsigned goal = old - (old % (unsigned)NB_CSR) + (unsigned)NB_CSR;
        while (true) {
            unsigned cur = *(volatile unsigned*)&g_barrier;
            if ((int)(cur - goal) >= 0) break;
        }
        __threadfence();
    }
    __syncthreads();
}

// bf16 helpers
__device__ __forceinline__ uint32_t bfpack(float x, float y) {
    __nv_bfloat162 t = __floats2bfloat162_rn(x, y);
    return *reinterpret_cast<uint32_t*>(&t);
}
__device__ __forceinline__ float bfhi(float x) {
    return __bfloat162float(__float2bfloat16(x));
}
__device__ __forceinline__ void mma_bf16(float* d, uint32_t a0, uint32_t a1,
                                         uint32_t a2, uint32_t a3,
                                         uint32_t b0, uint32_t b1) {
    asm volatile(
        "mma.sync.aligned.m16n8k16.row.col.f32.bf16.bf16.f32 "
        "{%0,%1,%2,%3}, {%4,%5,%6,%7}, {%8,%9}, {%0,%1,%2,%3};"
        : "+f"(d[0]), "+f"(d[1]), "+f"(d[2]), "+f"(d[3])
        : "r"(a0), "r"(a1), "r"(a2), "r"(a3), "r"(b0), "r"(b1));
}

// ---------------- K: transpose e_s [64,N_ENT] -> eT [N_ENT,64] ---------------
__global__ void transpose_kernel(const float* __restrict__ in, float* __restrict__ out) {
    __shared__ float tile[32][33];
    int tx = threadIdx.x, ty = threadIdx.y;
    int o_in = blockIdx.x * 32 + tx;
    int b_in = blockIdx.y * 32 + ty;
    tile[ty][tx] = in[(size_t)b_in * N_ENT + o_in];
    __syncthreads();
    int o_out = blockIdx.x * 32 + ty;
    int b_out = blockIdx.y * 32 + tx;
    out[(size_t)o_out * BSZ + b_out] = tile[tx][ty];
}

// ---------------- K: full CSR build in one persistent kernel -----------------
__global__ void __launch_bounds__(1024, 1)
csr_kernel(const int* __restrict__ subj, const int* __restrict__ rel,
           const int* __restrict__ obj, int* __restrict__ cnt,
           int* __restrict__ off, int* __restrict__ pos,
           int2* __restrict__ srS, int* __restrict__ bsum, int* __restrict__ bbase,
           float* __restrict__ predAcc) {
    __shared__ int s_scan[1024];
    __shared__ int s_b[256];
    const int tid = threadIdx.x, bid = blockIdx.x;
    const int gtid = bid * 1024 + tid;
    const int gstride = NB_CSR * 1024;

    for (int i = gtid; i <= N_ENT; i += gstride) cnt[i] = 0;
    for (int i = gtid; i < BSZ * DH + BSZ; i += gstride) predAcc[i] = 0.f;
    gsync();

    for (int t = gtid; t < N_TRI; t += gstride) atomicAdd(&cnt[obj[t]], 1);
    gsync();

    constexpr int CH = (N_ENT + NB_CSR - 1) / NB_CSR;  // 676
    const int base = bid * CH;
    const int m = min(CH, N_ENT - base);
    int val = (tid < m) ? cnt[base + tid] : 0;
    s_scan[tid] = val;
    __syncthreads();
    #pragma unroll
    for (int d = 1; d < 1024; d <<= 1) {
        int v = (tid >= d) ? s_scan[tid - d] : 0;
        __syncthreads();
        s_scan[tid] += v;
        __syncthreads();
    }
    int excl = s_scan[tid] - val;
    if (tid == 1023) bsum[bid] = s_scan[1023];
    gsync();

    if (bid == 0) {
        int bv = (tid < NB_CSR) ? bsum[tid] : 0;
        if (tid < 256) s_b[tid] = bv;
        __syncthreads();
        #pragma unroll
        for (int d = 1; d < 256; d <<= 1) {
            int v = 0;
            if (tid < 256 && tid >= d) v = s_b[tid - d];
            __syncthreads();
            if (tid < 256) s_b[tid] += v;
            __syncthreads();
        }
        if (tid < NB_CSR) bbase[tid] = s_b[tid] - bv;
    }
    gsync();

    int bb = bbase[bid];
    if (tid < m) {
        off[base + tid] = bb + excl;
        pos[base + tid] = bb + excl;
    }
    if (gtid == 0) off[N_ENT] = N_TRI;
    gsync();

    for (int t = gtid; t < N_TRI; t += gstride) {
        int o = obj[t];
        int p = atomicAdd(&pos[o], 1);
        srS[p] = make_int2(subj[t], rel[t]);
    }
}

// ---------------- per-step dense math (one block per batch row) --------------
__global__ void step_kernel(const float* __restrict__ qwh, const float* __restrict__ qemb,
                            const float* __restrict__ Wstep, const float* __restrict__ bstep,
                            const float* __restrict__ Wcq, const float* __restrict__ bcq,
                            const float* __restrict__ Wca, const float* __restrict__ bca,
                            const float* __restrict__ Wrel, const float* __restrict__ brel,
                            float* __restrict__ lastc, float* __restrict__ relT, int t) {
    __shared__ float s_qe[DH], s_lc[DH], s_qt[DH], s_cw[DH];
    __shared__ float s_log[MAXQ], s_dist[MAXQ];
    int b = blockIdx.x, tid = threadIdx.x;

    if (tid < DH) {
        s_qe[tid] = qemb[b * DH + tid];
        s_lc[tid] = (t == 0) ? 0.f : lastc[b * DH + tid];
    }
    __syncthreads();

    if (tid < DH) {
        const float* W = Wstep + t * DH * DH;
        float acc = bstep[t * DH + tid];
        for (int k = 0; k < DH; ++k) acc = fmaf(s_qe[k], W[k * DH + tid], acc);
        s_qt[tid] = tanhf(acc);
    }
    __syncthreads();

    if (tid < DH) {
        float acc = bcq[tid];
        if (t != 0)
            for (int k = 0; k < DH; ++k) acc = fmaf(s_lc[k], Wcq[k * DH + tid], acc);
        for (int k = 0; k < DH; ++k) acc = fmaf(s_qt[k], Wcq[(DH + k) * DH + tid], acc);
        s_cw[tid] = acc * Wca[tid];
    }
    __syncthreads();

    {
        int w = tid >> 5, lane = tid & 31;
        for (int q = w; q < MAXQ; q += 10) {
            const float* row = qwh + ((size_t)b * MAXQ + q) * DH;
            float acc = 0.f;
            for (int d = lane; d < DH; d += 32) acc = fmaf(s_cw[d], row[d], acc);
            acc = warp_sum(acc);
            if (lane == 0) s_log[q] = acc + bca[0];
        }
    }
    __syncthreads();

    if (tid < 32) {
        float v = s_log[tid];
        float m = warp_max(v);
        float e = expf(v - m);
        float s = warp_sum(e);
        s_dist[tid] = e / s;
    }
    __syncthreads();

    if (tid < DH) {
        const float* base = qwh + (size_t)b * MAXQ * DH + tid;
        float acc = 0.f;
        #pragma unroll
        for (int q = 0; q < MAXQ; ++q) acc = fmaf(s_dist[q], base[q * DH], acc);
        s_lc[tid] = acc;
        lastc[b * DH + tid] = acc;
    }
    __syncthreads();

    if (tid < 32) {
        float val = -1e30f;
        if (tid < N_REL) {
            float acc = brel[tid];
            for (int d = 0; d < DH; ++d) acc = fmaf(s_lc[d], Wrel[d * N_REL + tid], acc);
            val = acc;
        }
        float m = warp_max(val);
        float e = (tid < N_REL) ? expf(val - m) : 0.f;
        float s = warp_sum(e);
        if (tid < N_REL) relT[tid * BSZ + b] = e / s;
    }
}

// ---------------- follow via CSR: warp per object, 2-way unrolled ------------
__global__ void follow_kernel(const float* __restrict__ eCur, const float* __restrict__ relT,
                              const int* __restrict__ off, const int2* __restrict__ srS,
                              float* __restrict__ eNext) {
    int o = blockIdx.x * 8 + (threadIdx.x >> 5);
    int lane = threadIdx.x & 31;
    int beg = __ldg(off + o), end = __ldg(off + o + 1);
    float2 a0 = make_float2(0.f, 0.f);
    float2 a1 = make_float2(0.f, 0.f);
    int t = beg;
    for (; t + 1 < end; t += 2) {
        int2 s0 = __ldg(srS + t);
        int2 s1 = __ldg(srS + t + 1);
        float2 e0 = *reinterpret_cast<const float2*>(eCur + (size_t)s0.x * BSZ + 2 * lane);
        float2 r0 = *reinterpret_cast<const float2*>(relT + s0.y * BSZ + 2 * lane);
        float2 e1 = *reinterpret_cast<const float2*>(eCur + (size_t)s1.x * BSZ + 2 * lane);
        float2 r1 = *reinterpret_cast<const float2*>(relT + s1.y * BSZ + 2 * lane);
        a0.x = fmaf(e0.x, r0.x, a0.x);
        a0.y = fmaf(e0.y, r0.y, a0.y);
        a1.x = fmaf(e1.x, r1.x, a1.x);
        a1.y = fmaf(e1.y, r1.y, a1.y);
    }
    if (t < end) {
        int2 s0 = __ldg(srS + t);
        float2 e0 = *reinterpret_cast<const float2*>(eCur + (size_t)s0.x * BSZ + 2 * lane);
        float2 r0 = *reinterpret_cast<const float2*>(relT + s0.y * BSZ + 2 * lane);
        a0.x = fmaf(e0.x, r0.x, a0.x);
        a0.y = fmaf(e0.y, r0.y, a0.y);
    }
    *reinterpret_cast<float2*>(eNext + (size_t)o * BSZ + 2 * lane) =
        make_float2(a0.x + a1.x, a0.y + a1.y);
}

// ---------------- GEMM1 (pipelined fp32, proven): predAcc = eT^T @ emb -------
#define G1_SMEM (4 * 8 * 320 * 4 + 4 * 8 * 64 * 4)   // 49152

__global__ void __launch_bounds__(512, 1)
gemm1_kernel(const float* __restrict__ eT, const float* __restrict__ emb,
             float* __restrict__ predAcc) {
    extern __shared__ char sm1[];
    float* we = (float*)sm1;                       // [4][8][320]
    float* es = (float*)(sm1 + 4 * 8 * 320 * 4);   // [4][8][64]
    const int tid = threadIdx.x, lane = tid & 31, w = tid >> 5;
    const int b0 = w * 4;
    const int o0 = blockIdx.x * G1_OPB;
    const int m  = min(G1_OPB, N_ENT - o0);
    const int ng = (m + 7) >> 3;

    for (int i = tid; i < 4 * 8 * 20; i += 512) {
        int st = i / 160, rem = i % 160, row = rem / 20, c = 300 + rem % 20;
        we[st * 2560 + row * 320 + c] = 0.f;
    }

    unsigned long long acc[4][5];
    #pragma unroll
    for (int bi = 0; bi < 4; ++bi)
        #pragma unroll
        for (int j = 0; j < 5; ++j) acc[bi][j] = 0ull;
    float sum4[4] = {0.f, 0.f, 0.f, 0.f};

    auto issue = [&](int g) {
        int stage = g & 3;
        int ob = g * 8;
        #pragma unroll
        for (int r = 0; r < 2; ++r) {
            int idx = tid + r * 512;
            if (idx < 600) {
                int kk = idx / 75, f = idx % 75;
                int o = o0 + ob + kk;
                float* dst = &we[stage * 2560 + kk * 320 + f * 4];
                if (o < N_ENT) cpa16(s2u(dst), emb + (size_t)o * DH + f * 4);
                else *(float4*)dst = make_float4(0.f, 0.f, 0.f, 0.f);
            } else if (idx < 728) {
                int j = idx - 600;
                int kk = j >> 4, q = j & 15;
                int o = o0 + ob + kk;
                float* dst = &es[stage * 512 + kk * 64 + q * 4];
                if (o < N_ENT) cpa16(s2u(dst), eT + (size_t)o * BSZ + q * 4);
                else *(float4*)dst = make_float4(0.f, 0.f, 0.f, 0.f);
            }
        }
        CPA_COMMIT();
    };

    issue(0); issue(1); issue(2);

    for (int g = 0; g < ng; ++g) {
        cpa_wait_tail(g, ng);
        __syncthreads();
        int stage = g & 3;
        #pragma unroll 4
        for (int kk = 0; kk < 8; ++kk) {
            float4 e4 = *(const float4*)&es[stage * 512 + kk * 64 + b0];
            unsigned long long h0 = pk2(e4.x, e4.x), h1 = pk2(e4.y, e4.y);
            unsigned long long h2 = pk2(e4.z, e4.z), h3 = pk2(e4.w, e4.w);
            sum4[0] += e4.x; sum4[1] += e4.y; sum4[2] += e4.z; sum4[3] += e4.w;
            const float* wr = &we[stage * 2560 + kk * 320];
            #pragma unroll
            for (int j = 0; j < 5; ++j) {
                unsigned long long wv =
                    *(const unsigned long long*)(wr + (lane + 32 * j) * 2);
                fma2(acc[0][j], wv, h0);
                fma2(acc[1][j], wv, h1);
                fma2(acc[2][j], wv, h2);
                fma2(acc[3][j], wv, h3);
            }
        }
        __syncthreads();
        if (g + 3 < ng) issue(g + 3);
    }
    CPA_WAIT(0);

    #pragma unroll
    for (int j = 0; j < 5; ++j) {
        int dp = lane + 32 * j;
        if (dp < 150) {
            #pragma unroll
            for (int bi = 0; bi < 4; ++bi) {
                float2 a = upk(acc[bi][j]);
                atomicAdd(&predAcc[(b0 + bi) * DH + 2 * dp], a.x);
                atomicAdd(&predAcc[(b0 + bi) * DH + 2 * dp + 1], a.y);
            }
        }
    }
    if (lane == 0) {
        #pragma unroll
        for (int bi = 0; bi < 4; ++bi)
            atomicAdd(&predAcc[BSZ * DH + b0 + bi], sum4[bi]);
    }
}

// ---------------- h = relu(...) -> bf16 hi/lo arrays -------------------------
__global__ void h_kernel(const float* __restrict__ predAcc, const float* __restrict__ We1,
                         const float* __restrict__ be1,
                         __nv_bfloat16* __restrict__ hh, __nv_bfloat16* __restrict__ hl) {
    __shared__ float s_p[DH];
    int b = blockIdx.x, tid = threadIdx.x;
    float inv = 1.f / (predAcc[BSZ * DH + b] + 1e-6f);
    for (int i = tid; i < DH; i += 256) s_p[i] = predAcc[b * DH + i] * inv;
    __syncthreads();
    int d = blockIdx.y * 256 + tid;
    float acc = be1[d];
    for (int k = 0; k < DH; ++k) acc = fmaf(s_p[k], We1[k * D_CLS + d], acc);
    float v = fmaxf(acc, 0.f);
    __nv_bfloat16 hi = __float2bfloat16(v);
    hh[b * D_CLS + d] = hi;
    hl[b * D_CLS + d] = __float2bfloat16(v - __bfloat162float(hi));
}

// ---------------- GEMM2: HMMA bf16-split (R13-verified, verbatim) ------------
#define G2_KC    32
#define G2_NGC   (D_CLS / G2_KC)   // 32 chunks
#define G2_ROWW  260               // words per k-row (256 + 4 pad)
#define G2_SMEM  (2 * G2_KC * G2_ROWW * 4)   // 66560 B

__global__ void __launch_bounds__(512, 1)
gemm2_kernel(const __nv_bfloat16* __restrict__ hh, const __nv_bfloat16* __restrict__ hl,
             const float* __restrict__ We2, const float* __restrict__ be2,
             float* __restrict__ out) {
    extern __shared__ float Bs[];   // [2][32][260]
    const int tid = threadIdx.x, lane = tid & 31, w = tid >> 5;  // 16 warps
    const int g = lane >> 2, t = lane & 3;
    const int m0 = (w & 3) * 16;          // m-tile
    const int nbase = (w >> 2) * 64;      // n-range within 256

    for (int tile = blockIdx.x; tile < NTILES; tile += 148) {
        const int n0 = tile * 256;

        float acc[8][4];
        #pragma unroll
        for (int s = 0; s < 8; ++s)
            #pragma unroll
            for (int j = 0; j < 4; ++j) acc[s][j] = 0.f;

        auto issue = [&](int c) {
            int buf = c & 1;
            int k0 = c * G2_KC;
            #pragma unroll
            for (int r = 0; r < 4; ++r) {
                int u = tid + r * 512;            // 0..2047
                int row = u >> 6, q = u & 63;
                float* dst = &Bs[buf * G2_KC * G2_ROWW + row * G2_ROWW + q * 4];
                int n = n0 + q * 4;
                if (n < N_ENT)
                    cpa16(s2u(dst), We2 + (size_t)(k0 + row) * N_ENT + n);
                else
                    *(float4*)dst = make_float4(0.f, 0.f, 0.f, 0.f);
            }
            CPA_COMMIT();
        };

        issue(0);

        for (int c = 0; c < G2_NGC; ++c) {
            if (c + 1 < G2_NGC) issue(c + 1);
            if (c + 1 < G2_NGC) { CPA_WAIT(1); } else { CPA_WAIT(0); }
            __syncthreads();
            const float* B = &Bs[(c & 1) * G2_KC * G2_ROWW];
            const int kb = c * G2_KC;

            #pragma unroll
            for (int ks = 0; ks < 2; ++ks) {
                const int ka = kb + ks * 16 + 2 * t;
                const __nv_bfloat16* pa0 = hh + (m0 + g) * D_CLS + ka;
                const __nv_bfloat16* pa1 = hh + (m0 + g + 8) * D_CLS + ka;
                uint32_t ah0 = *(const uint32_t*)pa0;
                uint32_t ah1 = *(const uint32_t*)pa1;
                uint32_t ah2 = *(const uint32_t*)(pa0 + 8);
                uint32_t ah3 = *(const uint32_t*)(pa1 + 8);
                const __nv_bfloat16* pl0 = hl + (m0 + g) * D_CLS + ka;
                const __nv_bfloat16* pl1 = hl + (m0 + g + 8) * D_CLS + ka;
                uint32_t al0 = *(const uint32_t*)pl0;
                uint32_t al1 = *(const uint32_t*)pl1;
                uint32_t al2 = *(const uint32_t*)(pl0 + 8);
                uint32_t al3 = *(const uint32_t*)(pl1 + 8);

                #pragma unroll
                for (int sub = 0; sub < 8; ++sub) {
                    int nc = nbase + sub * 8 + g;
                    int kr = ks * 16 + 2 * t;
                    float b0 = B[(kr)     * G2_ROWW + nc];
                    float b1 = B[(kr + 1) * G2_ROWW + nc];
                    float b2 = B[(kr + 8) * G2_ROWW + nc];
                    float b3 = B[(kr + 9) * G2_ROWW + nc];
                    float h0 = bfhi(b0), h1 = bfhi(b1), h2 = bfhi(b2), h3 = bfhi(b3);
                    uint32_t bh0 = bfpack(b0, b1), bh1 = bfpack(b2, b3);
                    uint32_t bl0 = bfpack(b0 - h0, b1 - h1);
                    uint32_t bl1 = bfpack(b2 - h2, b3 - h3);
                    mma_bf16(acc[sub], ah0, ah1, ah2, ah3, bh0, bh1);
                    mma_bf16(acc[sub], ah0, ah1, ah2, ah3, bl0, bl1);
                    mma_bf16(acc[sub], al0, al1, al2, al3, bh0, bh1);
                }
            }
            __syncthreads();
        }

        #pragma unroll
        for (int sub = 0; sub < 8; ++sub) {
            int n = n0 + nbase + sub * 8 + 2 * t;
            if (n < N_ENT) {
                float2 bb = *(const float2*)(be2 + n);
                int r0 = m0 + g, r1 = m0 + g + 8;
                *(float2*)(out + (size_t)r0 * N_ENT + n) =
                    make_float2(acc[sub][0] + bb.x, acc[sub][1] + bb.y);
                *(float2*)(out + (size_t)r1 * N_ENT + n) =
                    make_float2(acc[sub][2] + bb.x, acc[sub][3] + bb.y);
            }
        }
        __syncthreads();
    }
}

// ---------------- launch -----------------------------------------------------
extern "C" void kernel_launch(void* const* d_in, const int* in_sizes, int n_in,
                              void* d_out, int out_size) {
    const float* qwh   = (const float*)d_in[0];
    const float* qemb  = (const float*)d_in[1];
    const float* e_s   = (const float*)d_in[2];
    const float* Wstep = (const float*)d_in[3];
    const float* bstep = (const float*)d_in[4];
    const float* Wcq   = (const float*)d_in[5];
    const float* bcq   = (const float*)d_in[6];
    const float* Wca   = (const float*)d_in[7];
    const float* bca   = (const float*)d_in[8];
    const float* Wrel  = (const float*)d_in[9];
    const float* brel  = (const float*)d_in[10];
    const float* emb   = (const float*)d_in[11];
    const float* We1   = (const float*)d_in[12];
    const float* be1   = (const float*)d_in[13];
    const float* We2   = (const float*)d_in[14];
    const float* be2   = (const float*)d_in[15];
    const int*   subj  = (const int*)d_in[16];
    const int*   rel   = (const int*)d_in[17];
    const int*   obj   = (const int*)d_in[18];
    float* out = (float*)d_out;

    float *eA, *eB, *lastc, *relT, *predAcc;
    __nv_bfloat16 *hh, *hl;
    int *cnt, *off, *pos, *bsum, *bbase;
    int2* srS;
    cudaGetSymbolAddress((void**)&eA, g_eA);
    cudaGetSymbolAddress((void**)&eB, g_eB);
    cudaGetSymbolAddress((void**)&lastc, g_lastc);
    cudaGetSymbolAddress((void**)&relT, g_relT);
    cudaGetSymbolAddress((void**)&predAcc, g_predAcc);
    cudaGetSymbolAddress((void**)&hh, g_hh);
    cudaGetSymbolAddress((void**)&hl, g_hl);
    cudaGetSymbolAddress((void**)&cnt, g_cnt);
    cudaGetSymbolAddress((void**)&off, g_off);
    cudaGetSymbolAddress((void**)&pos, g_pos);
    cudaGetSymbolAddress((void**)&srS, g_srS);
    cudaGetSymbolAddress((void**)&bsum, g_bsum);
    cudaGetSymbolAddress((void**)&bbase, g_bbase);

    cudaFuncSetAttribute(gemm2_kernel, cudaFuncAttributeMaxDynamicSharedMemorySize,
                         G2_SMEM);
    cudaFuncSetAttribute(gemm1_kernel, cudaFuncAttributeMaxDynamicSharedMemorySize,
                         G1_SMEM);

    transpose_kernel<<<dim3(N_ENT / 32, BSZ / 32), dim3(32, 32)>>>(e_s, eA);
    step_kernel<<<BSZ, 320>>>(qwh, qemb, Wstep, bstep, Wcq, bcq, Wca, bca,
                              Wrel, brel, lastc, relT, 0);
    csr_kernel<<<NB_CSR, 1024>>>(subj, rel, obj, cnt, off, pos, srS, bsum, bbase,
                                 predAcc);

    float* cur = eA;
    float* nxt = eB;
    for (int t = 0; t < 3; ++t) {
        if (t > 0)
            step_kernel<<<BSZ, 320>>>(qwh, qemb, Wstep, bstep, Wcq, bcq, Wca, bca,
                                      Wrel, brel, lastc, relT, t);
        follow_kernel<<<N_ENT / 8, 256>>>(cur, relT, off, srS, nxt);
        float* tmp = cur; cur = nxt; nxt = tmp;
    }

    gemm1_kernel<<<148, 512, G1_SMEM>>>(cur, emb, predAcc);
    h_kernel<<<dim3(BSZ, D_CLS / 256), 256>>>(predAcc, We1, be1, hh, hl);
    gemm2_kernel<<<148, 512, G2_SMEM>>>(hh, hl, We2, be2, out);
}